// round 2
// baseline (speedup 1.0000x reference)
#include <cuda_runtime.h>

// Problem constants
#define BB      2
#define NN      512
#define CC      64
#define HH      8
#define THREADS 512   // 16 warps; warp w owns rows [w*32, w*32+32) of its (b,m)

__device__ __forceinline__ float dot4(float4 a, float4 b, float acc) {
    acc = fmaf(a.x, b.x, acc);
    acc = fmaf(a.y, b.y, acc);
    acc = fmaf(a.z, b.z, acc);
    acc = fmaf(a.w, b.w, acc);
    return acc;
}

__global__ __launch_bounds__(THREADS)
void mha_fused2(const float4* __restrict__ q4,
                const float4* __restrict__ k4,
                const float*  __restrict__ roi,
                const float4* __restrict__ W4,
                const float*  __restrict__ bias,
                float4*       __restrict__ out4)
{
    // W: 8 heads x 32 float4 (idx h*32 + c4 : c4<16 = Wq, 16..31 = Wk)
    __shared__ float4 wsm[HH * 32];
    __shared__ float  roism[NN];
    __shared__ float  attn[NN * HH];      // 16 KB staging of exp(logit)*roi
    __shared__ float  wsum[16 * HH];      // per-warp per-head partial sums
    __shared__ float  invs[HH];
    __shared__ float  bs[HH];

    const int tid  = threadIdx.x;
    const int row  = blockIdx.x;                 // b*N + m
    const int lane = tid & 31;
    const int warp = tid >> 5;
    const int rid  = lane >> 3;                  // 0..3 : row within pass
    const int cl   = lane & 7;                   // 0..7 : c-lane / head owner

    const float4* qb = q4 + (size_t)row * (NN * CC / 4);
    const float4* kb = k4 + (size_t)row * (NN * CC / 4);

    if (tid < HH * 32) wsm[tid] = W4[tid];
    roism[tid] = roi[(size_t)row * NN + tid];
    if (tid < HH) bs[tid] = bias[tid];
    __syncthreads();

    const float breg = bs[cl];                   // bias for the head this lane owns
    float psum = 0.f;
    const int nbase = warp * 32;

    #pragma unroll
    for (int p = 0; p < 8; ++p) {
        const int n = nbase + p * 4 + rid;
        // Perfectly coalesced: per LDG.128, 4 rows x 128B contiguous segments
        const float4 qv0 = qb[n * 16 + cl];
        const float4 qv1 = qb[n * 16 + cl + 8];
        const float4 kv0 = kb[n * 16 + cl];
        const float4 kv1 = kb[n * 16 + cl + 8];

        float v[8];
        #pragma unroll
        for (int h = 0; h < 8; ++h) {
            const float4 wq0 = wsm[h * 32 + cl];
            const float4 wq1 = wsm[h * 32 + cl + 8];
            const float4 wk0 = wsm[h * 32 + 16 + cl];
            const float4 wk1 = wsm[h * 32 + 24 + cl];
            float a = dot4(qv0, wq0, 0.f);
            a = dot4(qv1, wq1, a);
            a = dot4(kv0, wk0, a);
            a = dot4(kv1, wk1, a);
            v[h] = a;
        }

        // Exchange-reduce over the 8 c-lanes: 7 shfl, lane cl ends with head cl.
        const bool b0 = cl & 1;
        float w0 = (b0 ? v[1] : v[0]) + __shfl_xor_sync(0xffffffffu, b0 ? v[0] : v[1], 1);
        float w1 = (b0 ? v[3] : v[2]) + __shfl_xor_sync(0xffffffffu, b0 ? v[2] : v[3], 1);
        float w2 = (b0 ? v[5] : v[4]) + __shfl_xor_sync(0xffffffffu, b0 ? v[4] : v[5], 1);
        float w3 = (b0 ? v[7] : v[6]) + __shfl_xor_sync(0xffffffffu, b0 ? v[6] : v[7], 1);
        const bool b1 = cl & 2;
        float x0 = (b1 ? w1 : w0) + __shfl_xor_sync(0xffffffffu, b1 ? w0 : w1, 2);
        float x1 = (b1 ? w3 : w2) + __shfl_xor_sync(0xffffffffu, b1 ? w2 : w3, 2);
        const bool b2 = cl & 4;
        float r  = (b2 ? x1 : x0) + __shfl_xor_sync(0xffffffffu, b2 ? x0 : x1, 4);
        // r == full logit for (row n, head cl)

        const float val = __expf(r + breg) * roism[n];
        psum += val;
        attn[n * HH + cl] = val;   // conflict-free: word index ≡ lane (mod 32)
    }

    // Per-warp per-head sums: combine the 4 rid lanes
    psum += __shfl_xor_sync(0xffffffffu, psum, 8);
    psum += __shfl_xor_sync(0xffffffffu, psum, 16);
    if (lane < 8) wsum[warp * 8 + lane] = psum;
    __syncthreads();

    if (tid < HH) {
        float s = 0.f;
        #pragma unroll
        for (int w = 0; w < 16; ++w) s += wsum[w * 8 + tid];
        invs[tid] = 1.0f / s;
    }
    __syncthreads();

    // Coalesced normalize + store: 1024 float4, 2 per thread
    float4* ob = out4 + (size_t)row * (NN * HH / 4);
    const float4* at4 = (const float4*)attn;
    const float4* iv4 = (const float4*)invs;
    #pragma unroll
    for (int i = tid; i < NN * HH / 4; i += THREADS) {
        float4 a  = at4[i];
        float4 iv = iv4[i & 1];
        a.x *= iv.x; a.y *= iv.y; a.z *= iv.z; a.w *= iv.w;
        ob[i] = a;
    }
}

extern "C" void kernel_launch(void* const* d_in, const int* in_sizes, int n_in,
                              void* d_out, int out_size) {
    const float4* q   = (const float4*)d_in[0];
    const float4* k   = (const float4*)d_in[1];
    const float*  roi = (const float*)d_in[2];
    const float4* W   = (const float4*)d_in[3];
    const float*  b   = (const float*)d_in[4];
    float4* out = (float4*)d_out;

    mha_fused2<<<BB * NN, THREADS>>>(q, k, roi, W, b, out);
}

// round 3
// speedup vs baseline: 3.5274x; 3.5274x over previous
#include <cuda_runtime.h>

// Problem constants
#define BB      2
#define NN      512
#define CC      64
#define HH      8
#define TN      128                 // rows per staged tile
#define NTILES  (NN / TN)           // 4
#define THREADS 512
#define DYN_BYTES (TN * 32 * 16)    // [128 rows][32 float4 = q(16)|k(16)] = 64 KB

typedef unsigned long long ull;

__device__ __forceinline__ ull pack2(float lo, float hi) {
    ull r; asm("mov.b64 %0, {%1, %2};" : "=l"(r) : "f"(lo), "f"(hi)); return r;
}
__device__ __forceinline__ ull fma2(ull a, ull b, ull c) {
    ull d; asm("fma.rn.f32x2 %0, %1, %2, %3;" : "=l"(d) : "l"(a), "l"(b), "l"(c)); return d;
}
__device__ __forceinline__ ull mul2(ull a, ull b) {
    ull d; asm("mul.rn.f32x2 %0, %1, %2;" : "=l"(d) : "l"(a), "l"(b)); return d;
}
__device__ __forceinline__ float unpadd(ull a) {
    float lo, hi; asm("mov.b64 {%0, %1}, %2;" : "=f"(lo), "=f"(hi) : "l"(a)); return lo + hi;
}

__global__ __launch_bounds__(THREADS, 2)
void mha_fused3(const float4* __restrict__ q4,
                const float4* __restrict__ k4,
                const float*  __restrict__ roi,
                const float4* __restrict__ W4,
                const float*  __restrict__ bias,
                float4*       __restrict__ out4)
{
    extern __shared__ float4 tile[];      // [TN][32] : q f4 0..15, k f4 16..31
    __shared__ float attn[NN * HH];       // 16 KB
    __shared__ float roism[NN];
    __shared__ float wsum[16 * HH];
    __shared__ float invs[HH];

    const int tid  = threadIdx.x;
    const int lane = tid & 31;
    const int warp = tid >> 5;
    const int row  = blockIdx.x;          // b*N + m

    // Lane-resident W: lane L holds [Wq||Wk] float4 #L for all 8 heads, packed f32x2.
    ull wr[HH][2];
    #pragma unroll
    for (int h = 0; h < HH; ++h) {
        float4 w = W4[h * 32 + lane];
        wr[h][0] = pack2(w.x, w.y);
        wr[h][1] = pack2(w.z, w.w);
    }
    const float breg = bias[lane & 7];

    roism[tid] = roi[(size_t)row * NN + tid];

    const float4* qg = q4 + (size_t)row * (NN * CC / 4);
    const float4* kg = k4 + (size_t)row * (NN * CC / 4);

    float psum = 0.f;

    #pragma unroll
    for (int t = 0; t < NTILES; ++t) {
        // ---- stage 128 rows of q||k, fully coalesced ----
        #pragma unroll
        for (int i = tid; i < TN * 16; i += THREADS) {
            int r = i >> 4, c = i & 15;
            tile[r * 32 + c]      = qg[t * (TN * 16) + i];
            tile[r * 32 + 16 + c] = kg[t * (TN * 16) + i];
        }
        __syncthreads();

        // ---- each warp: 8 rows; one LDS.128 per row; W from registers ----
        #pragma unroll
        for (int rr = 0; rr < 8; ++rr) {
            const int nl = warp * 8 + rr;
            const float4 qv = tile[nl * 32 + lane];
            const ull a01 = pack2(qv.x, qv.y);
            const ull a23 = pack2(qv.z, qv.w);

            float v[HH];
            #pragma unroll
            for (int h = 0; h < HH; ++h)
                v[h] = unpadd(fma2(a01, wr[h][0], mul2(a23, wr[h][1])));

            // 9-shfl value-blocked butterfly: lane L ends with head L&7, full 32-lane sum
            const bool b0 = lane & 1;
            float w0 = (b0 ? v[1] : v[0]) + __shfl_xor_sync(0xffffffffu, b0 ? v[0] : v[1], 1);
            float w1 = (b0 ? v[3] : v[2]) + __shfl_xor_sync(0xffffffffu, b0 ? v[2] : v[3], 1);
            float w2 = (b0 ? v[5] : v[4]) + __shfl_xor_sync(0xffffffffu, b0 ? v[4] : v[5], 1);
            float w3 = (b0 ? v[7] : v[6]) + __shfl_xor_sync(0xffffffffu, b0 ? v[6] : v[7], 1);
            const bool b1 = lane & 2;
            float x0 = (b1 ? w1 : w0) + __shfl_xor_sync(0xffffffffu, b1 ? w0 : w1, 2);
            float x1 = (b1 ? w3 : w2) + __shfl_xor_sync(0xffffffffu, b1 ? w2 : w3, 2);
            const bool b2 = lane & 4;
            float r1 = (b2 ? x1 : x0) + __shfl_xor_sync(0xffffffffu, b2 ? x0 : x1, 4);
            r1 += __shfl_xor_sync(0xffffffffu, r1, 8);
            r1 += __shfl_xor_sync(0xffffffffu, r1, 16);
            // r1 = logit(row n, head lane&7)

            const int n = t * TN + nl;
            const float val = __expf(r1 + breg) * roism[n];
            psum += val;
            if (lane < 8) attn[n * HH + lane] = val;
        }
        __syncthreads();   // tile consumed before next stage overwrites
    }

    // ---- per-head sums ----
    if (lane < 8) wsum[warp * HH + lane] = psum;
    __syncthreads();
    if (tid < HH) {
        float s = 0.f;
        #pragma unroll
        for (int w = 0; w < 16; ++w) s += wsum[w * HH + tid];
        invs[tid] = 1.0f / s;
    }
    __syncthreads();

    // ---- coalesced normalize + store ----
    float4* ob = out4 + (size_t)row * (NN * HH / 4);
    const float4* at4 = (const float4*)attn;
    const float4* iv4 = (const float4*)invs;
    #pragma unroll
    for (int i = tid; i < NN * HH / 4; i += THREADS) {
        float4 a  = at4[i];
        float4 iv = iv4[i & 1];
        a.x *= iv.x; a.y *= iv.y; a.z *= iv.z; a.w *= iv.w;
        ob[i] = a;
    }
}

extern "C" void kernel_launch(void* const* d_in, const int* in_sizes, int n_in,
                              void* d_out, int out_size) {
    const float4* q   = (const float4*)d_in[0];
    const float4* k   = (const float4*)d_in[1];
    const float*  roi = (const float*)d_in[2];
    const float4* W   = (const float4*)d_in[3];
    const float*  b   = (const float*)d_in[4];
    float4* out = (float4*)d_out;

    cudaFuncSetAttribute(mha_fused3,
                         cudaFuncAttributeMaxDynamicSharedMemorySize, DYN_BYTES);
    mha_fused3<<<BB * NN, THREADS, DYN_BYTES>>>(q, k, roi, W, b, out);
}

// round 6
// speedup vs baseline: 4.1708x; 1.1824x over previous
#include <cuda_runtime.h>

// Problem constants
#define BB      2
#define NN      512
#define CC      64
#define HH      8
#define TN      64                   // rows per staged tile
#define NT      (NN / TN)            // 8 tiles
#define THREADS 512                  // 16 warps; each warp: 4 rows per tile
#define BUF_F4  (TN * 32)            // 2048 float4 per buffer
#define DYN_BYTES (2 * BUF_F4 * 16)  // 64 KB double buffer

typedef unsigned long long ull;

__device__ __forceinline__ ull pack2(float lo, float hi) {
    ull r; asm("mov.b64 %0, {%1, %2};" : "=l"(r) : "f"(lo), "f"(hi)); return r;
}
__device__ __forceinline__ ull fma2(ull a, ull b, ull c) {
    ull d; asm("fma.rn.f32x2 %0, %1, %2, %3;" : "=l"(d) : "l"(a), "l"(b), "l"(c)); return d;
}
__device__ __forceinline__ ull mul2(ull a, ull b) {
    ull d; asm("mul.rn.f32x2 %0, %1, %2;" : "=l"(d) : "l"(a), "l"(b)); return d;
}
__device__ __forceinline__ float unpadd(ull a) {
    float lo, hi; asm("mov.b64 {%0, %1}, %2;" : "=f"(lo), "=f"(hi) : "l"(a)); return lo + hi;
}
__device__ __forceinline__ void cpasync16(unsigned int dst, const void* src) {
    asm volatile("cp.async.cg.shared.global [%0], [%1], 16;" :: "r"(dst), "l"(src));
}

__global__ __launch_bounds__(THREADS, 2)
void mha_fused5(const float4* __restrict__ q4,
                const float4* __restrict__ k4,
                const float*  __restrict__ roi,
                const float4* __restrict__ W4,
                const float*  __restrict__ bias,
                float4*       __restrict__ out4)
{
    extern __shared__ float4 tile[];      // 2 x [TN][32] : q f4 0..15, k f4 16..31
    __shared__ float attn[NN * HH];       // 16 KB
    __shared__ float roism[NN];
    __shared__ float wsum[16 * HH];
    __shared__ float invs[HH];

    const int tid  = threadIdx.x;
    const int lane = tid & 31;
    const int warp = tid >> 5;
    const int row  = blockIdx.x;          // b*N + m

    // Lane-resident W: lane L holds [Wq||Wk] float4 #L for all 8 heads (f32x2-packed)
    ull wr[HH][2];
    #pragma unroll
    for (int h = 0; h < HH; ++h) {
        float4 w = W4[h * 32 + lane];
        wr[h][0] = pack2(w.x, w.y);
        wr[h][1] = pack2(w.z, w.w);
    }
    const float breg = bias[lane & 7];

    roism[tid] = roi[(size_t)row * NN + tid];

    const float4* qg = q4 + (size_t)row * (NN * CC / 4);
    const float4* kg = k4 + (size_t)row * (NN * CC / 4);
    const unsigned int smem_base = (unsigned int)__cvta_generic_to_shared(tile);

    // --- async stage of one tile (64 rows of q||k) into buffer b ---
    auto stage = [&](int t, int b) {
        const unsigned int dstb = smem_base + b * (BUF_F4 * 16);
        #pragma unroll
        for (int j = 0; j < 2; ++j) {
            const int idx = tid + j * 512;         // 0..1023 over 64x16 float4
            const int r = idx >> 4, c = idx & 15;
            cpasync16(dstb + (r * 32 + c) * 16,      qg + t * (TN * 16) + idx);
            cpasync16(dstb + (r * 32 + 16 + c) * 16, kg + t * (TN * 16) + idx);
        }
        asm volatile("cp.async.commit_group;" ::: "memory");
    };

    stage(0, 0);

    float psum = 0.f;

    #pragma unroll
    for (int t = 0; t < NT; ++t) {
        if (t < NT - 1) {
            stage(t + 1, (t + 1) & 1);
            asm volatile("cp.async.wait_group 1;" ::: "memory");
        } else {
            asm volatile("cp.async.wait_group 0;" ::: "memory");
        }
        __syncthreads();   // tile t visible to all warps

        const float4* tb = tile + (t & 1) * BUF_F4;

        #pragma unroll
        for (int rr = 0; rr < 4; ++rr) {
            const int nl = warp * 4 + rr;
            const float4 qv = tb[nl * 32 + lane];  // conflict-free per quarter-warp
            const ull a01 = pack2(qv.x, qv.y);
            const ull a23 = pack2(qv.z, qv.w);

            float v[HH];
            #pragma unroll
            for (int h = 0; h < HH; ++h)
                v[h] = unpadd(fma2(a01, wr[h][0], mul2(a23, wr[h][1])));

            // 9-shfl value-blocked butterfly: lane L ends with head L&7, full 32-lane sum
            const bool b0 = lane & 1;
            float w0 = (b0 ? v[1] : v[0]) + __shfl_xor_sync(0xffffffffu, b0 ? v[0] : v[1], 1);
            float w1 = (b0 ? v[3] : v[2]) + __shfl_xor_sync(0xffffffffu, b0 ? v[2] : v[3], 1);
            float w2 = (b0 ? v[5] : v[4]) + __shfl_xor_sync(0xffffffffu, b0 ? v[4] : v[5], 1);
            float w3 = (b0 ? v[7] : v[6]) + __shfl_xor_sync(0xffffffffu, b0 ? v[6] : v[7], 1);
            const bool b1 = lane & 2;
            float x0 = (b1 ? w1 : w0) + __shfl_xor_sync(0xffffffffu, b1 ? w0 : w1, 2);
            float x1 = (b1 ? w3 : w2) + __shfl_xor_sync(0xffffffffu, b1 ? w2 : w3, 2);
            const bool b2 = lane & 4;
            float r1 = (b2 ? x1 : x0) + __shfl_xor_sync(0xffffffffu, b2 ? x0 : x1, 4);
            r1 += __shfl_xor_sync(0xffffffffu, r1, 8);
            r1 += __shfl_xor_sync(0xffffffffu, r1, 16);
            // r1 = logit(row n, head lane&7)

            const int n = t * TN + nl;
            const float val = __expf(r1 + breg) * roism[n];
            psum += val;
            if (lane < 8) attn[n * HH + lane] = val;
        }
        __syncthreads();   // tile consumed before its buffer is restaged
    }

    // ---- per-head sums ----
    if (lane < 8) wsum[warp * HH + lane] = psum;
    __syncthreads();
    if (tid < HH) {
        float s = 0.f;
        #pragma unroll
        for (int w = 0; w < 16; ++w) s += wsum[w * HH + tid];
        invs[tid] = 1.0f / s;
    }
    __syncthreads();

    // ---- coalesced normalize + store ----
    float4* ob = out4 + (size_t)row * (NN * HH / 4);
    const float4* at4 = (const float4*)attn;
    const float4* iv4 = (const float4*)invs;
    #pragma unroll
    for (int i = tid; i < NN * HH / 4; i += THREADS) {
        float4 a  = at4[i];
        float4 iv = iv4[i & 1];
        a.x *= iv.x; a.y *= iv.y; a.z *= iv.z; a.w *= iv.w;
        ob[i] = a;
    }
}

extern "C" void kernel_launch(void* const* d_in, const int* in_sizes, int n_in,
                              void* d_out, int out_size) {
    const float4* q   = (const float4*)d_in[0];
    const float4* k   = (const float4*)d_in[1];
    const float*  roi = (const float*)d_in[2];
    const float4* W   = (const float4*)d_in[3];
    const float*  b   = (const float*)d_in[4];
    float4* out = (float4*)d_out;

    cudaFuncSetAttribute(mha_fused5,
                         cudaFuncAttributeMaxDynamicSharedMemorySize, DYN_BYTES);
    mha_fused5<<<BB * NN, THREADS, DYN_BYTES>>>(q, k, roi, W, b, out);
}